// round 6
// baseline (speedup 1.0000x reference)
#include <cuda_runtime.h>

// EffectiveProbability: post = normalize(p * (CM @ c)) per pixel.
// Input row-normalizations cancel against the output normalization -> skipped.
//
// prior/current [8,21,512,512] f32, cm [21,21] f32, out [B*H*W,21] f32.
//
// R6: R5 dual-pixel chains (validated: L1 62->44%) + occupancy fix.
// Pair (pA, pA+256) shares the same batch index (512 | 2^18), so
// baseB = baseA + 256 -> fewer address regs. __launch_bounds__(256,4)
// caps regs at 64 -> 4 blocks/SM (occ ~50%) to raise outstanding LDGs
// and DRAM utilization (the measured binder: DRAM ~51% at 3 blocks/SM).

#define NCLS 21
#define HWSHIFT 18              // H*W = 512*512 = 2^18
#define HWSZ (1 << HWSHIFT)
#define BLOCK 256
#define PPB (2 * BLOCK)         // 512 pixels per block; 512 | 2^18

__global__ __launch_bounds__(BLOCK, 4)
void eff_prob_kernel(const float* __restrict__ prior,
                     const float* __restrict__ current,
                     const float* __restrict__ cm,
                     float* __restrict__ out,
                     int npix)
{
    __shared__ float s_cm[NCLS * NCLS];
    __shared__ float s_out[PPB * NCLS];      // 43008 B
    __shared__ float s_inv[PPB];

    const int tid = threadIdx.x;
    for (int i = tid; i < NCLS * NCLS; i += BLOCK) s_cm[i] = cm[i];
    __syncthreads();

    const int blk_base = blockIdx.x * PPB;
    const int pA = blk_base + tid;            // smem row tid
    const int pB = pA + BLOCK;                // smem row BLOCK+tid, same batch as pA

    if (pB < npix) {
        const int b  = pA >> HWSHIFT;         // == pB >> HWSHIFT
        const int hw = pA & (HWSZ - 1);
        const size_t baseA = ((size_t)b * NCLS << HWSHIFT) + hw;
        const float* __restrict__ cpA = current + baseA;   // pixel B = +BLOCK elems
        const float* __restrict__ ppA = prior + baseA;

        // Front-batched coalesced loads: 42 independent LDG.32 per pixel pair.
        float cvA[NCLS], cvB[NCLS];
        #pragma unroll
        for (int j = 0; j < NCLS; j++) {
            const size_t o = (size_t)j << HWSHIFT;
            cvA[j] = cpA[o];
            cvB[j] = cpA[o + BLOCK];
        }

        // Prior prefetch ring, depth 2 (same pointer, +BLOCK for pixel B).
        float pA0 = ppA[0],                      pB0 = ppA[BLOCK];
        float pA1 = ppA[(size_t)1 << HWSHIFT],   pB1 = ppA[((size_t)1 << HWSHIFT) + BLOCK];

        float accA = 0.0f, accB = 0.0f;
        float* soA = s_out + tid * NCLS;              // stride 21: conflict-free
        float* soB = s_out + (BLOCK + tid) * NCLS;

        #pragma unroll
        for (int i = 0; i < NCLS; i++) {
            const float pa = pA0, pb = pB0;
            pA0 = pA1; pB0 = pB1;
            if (i + 2 < NCLS) {
                const size_t o = (size_t)(i + 2) << HWSHIFT;
                pA1 = ppA[o];
                pB1 = ppA[o + BLOCK];
            }
            float sA = 0.0f, sB = 0.0f;
            #pragma unroll
            for (int j = 0; j < NCLS; j++) {
                const float w = s_cm[i * NCLS + j];   // one LDS.32 broadcast, 2 FFMAs
                sA = fmaf(w, cvA[j], sA);
                sB = fmaf(w, cvB[j], sB);
            }
            const float tA = pa * sA;
            const float tB = pb * sB;
            soA[i] = tA;
            soB[i] = tB;
            accA += tA;
            accB += tB;
        }
        s_inv[tid]         = 1.0f / accA;
        s_inv[BLOCK + tid] = 1.0f / accB;
    } else if (pA < npix) {
        // Tail safety (never taken for npix = 2^21): single-pixel scalar path.
        const int b  = pA >> HWSHIFT;
        const int hw = pA & (HWSZ - 1);
        const size_t base = ((size_t)b * NCLS << HWSHIFT) + hw;
        float cv[NCLS];
        #pragma unroll
        for (int j = 0; j < NCLS; j++) cv[j] = current[base + ((size_t)j << HWSHIFT)];
        float acc = 0.0f;
        float* so = s_out + tid * NCLS;
        #pragma unroll
        for (int i = 0; i < NCLS; i++) {
            float s = 0.0f;
            #pragma unroll
            for (int j = 0; j < NCLS; j++) s = fmaf(s_cm[i * NCLS + j], cv[j], s);
            const float t = prior[base + ((size_t)i << HWSHIFT)] * s;
            so[i] = t;
            acc += t;
        }
        s_inv[tid] = 1.0f / acc;
    }
    __syncthreads();

    // Flush [PPB, 21] tile linearly: fully coalesced 128B stores.
    const long out_base = (long)blk_base * NCLS;
    const int  valid    = min(PPB, npix - blk_base);
    const int  count    = valid * NCLS;
    for (int k = tid; k < count; k += BLOCK)
        out[out_base + k] = s_out[k] * s_inv[k / NCLS];   // const-div -> magic mul
}

extern "C" void kernel_launch(void* const* d_in, const int* in_sizes, int n_in,
                              void* d_out, int out_size)
{
    const float* prior   = (const float*)d_in[0];
    const float* current = (const float*)d_in[1];
    const float* cm      = (const float*)d_in[2];
    float*       out     = (float*)d_out;

    const int npix = in_sizes[0] / NCLS;   // B*H*W
    const int grid = (npix + PPB - 1) / PPB;
    eff_prob_kernel<<<grid, BLOCK>>>(prior, current, cm, out, npix);
}